// round 1
// baseline (speedup 1.0000x reference)
#include <cuda_runtime.h>
#include <math.h>

#define B_AG 32768
#define DID  512
#define HID  1024
#define NOPT 8
#define NACT 16

#define TB 64
#define TN 64
#define NTHREADS 256

#define OBS_STRIDE 516
#define WS_STRIDE  68
#define HS_STRIDE  68
#define HW_STRIDE  20

#define OBS_OFF 0
#define OBS_SZ  (TB*OBS_STRIDE)
#define WS_OFF  (OBS_OFF+OBS_SZ)
#define WS_SZ   (TN*WS_STRIDE)
#define HS_OFF  (WS_OFF+WS_SZ)
#define HS_SZ   (TB*HS_STRIDE)
#define HW_OFF  (HS_OFF+HS_SZ)
#define HW_SZ   (TN*HW_STRIDE)
#define MISC_OFF (HW_OFF+HW_SZ)
#define MISC_SZ  160
#define SMEM_FLOATS (MISC_OFF+MISC_SZ)
#define SMEM_BYTES  (SMEM_FLOATS*4)

__device__ int g_opt_cnt[NOPT];
__device__ int g_opt_list[NOPT*B_AG];

__global__ void init_kernel() {
    if (threadIdx.x < NOPT) g_opt_cnt[threadIdx.x] = 0;
}

// ---------------------------------------------------------------------------
// Phase A: meta policy + termination net, fused. Produces meta outputs and the
// per-option compacted agent lists for phase B.
// ---------------------------------------------------------------------------
__global__ void __launch_bounds__(NTHREADS, 1)
meta_term_kernel(const float* __restrict__ obs,
                 const int*   __restrict__ dones,
                 const int*   __restrict__ exec_opt,
                 const float* __restrict__ Wm1,
                 const float* __restrict__ bm1,
                 const float* __restrict__ Wm_pi,
                 const float* __restrict__ Wm_v,
                 const float* __restrict__ Wt1,
                 const float* __restrict__ Wt2,
                 float* __restrict__ out)
{
    extern __shared__ float sm[];
    float* obs_s  = sm + OBS_OFF;
    float* ws     = sm + WS_OFF;
    float* hs     = sm + HS_OFF;
    float* hw     = sm + HW_OFF;
    float* bias_s = sm + MISC_OFF;          // 64 floats
    int*   icnt   = (int*)(sm + MISC_OFF + 64); // counters

    const int t    = threadIdx.x;
    const int tx   = t & 15;
    const int ty   = t >> 4;
    const int row4 = t >> 2;
    const int j4   = t & 3;
    const int g0   = blockIdx.x * TB;

    // load obs tile [64 x 512] (coalesced, float4)
    for (int i = t; i < TB*(DID/4); i += NTHREADS) {
        int r = i >> 7, c4 = i & 127;
        float4 v = *(const float4*)(obs + (size_t)(g0 + r)*DID + c4*4);
        *(float4*)(obs_s + r*OBS_STRIDE + c4*4) = v;
    }

    // head accumulators (persist across H tiles)
    float m0 = 0.f, m1 = 0.f, m2 = 0.f;   // meta: logits j4, j4+4, (+value if j4==0)
    float t0 = 0.f, t1 = 0.f;             // term: logits j4, j4+4

    for (int ht = 0; ht < HID/TN; ++ht) {
        const int hbase = ht * TN;
        __syncthreads();  // protect hw/bias/hs from prior-tile readers
        if (t < TN) {
            const float* wp = Wm_pi + (size_t)(hbase + t)*NOPT;
            #pragma unroll
            for (int o = 0; o < NOPT; ++o) hw[t*HW_STRIDE + o] = wp[o];
            hw[t*HW_STRIDE + 8] = Wm_v[hbase + t];
            const float* wt = Wt2 + (size_t)(hbase + t)*NOPT;
            #pragma unroll
            for (int o = 0; o < NOPT; ++o) hw[t*HW_STRIDE + 9 + o] = wt[o];
            bias_s[t] = bm1[hbase + t];
        }

        #pragma unroll
        for (int net = 0; net < 2; ++net) {
            const float* Wg = net ? Wt1 : Wm1;
            float acc[4][4];
            #pragma unroll
            for (int i = 0; i < 4; ++i)
                #pragma unroll
                for (int jj = 0; jj < 4; ++jj) acc[i][jj] = 0.f;

            for (int kc = 0; kc < DID; kc += 64) {
                __syncthreads();
                for (int i = t; i < 64*16; i += NTHREADS) {
                    int kk = i >> 4, c4 = i & 15;
                    float4 v = *(const float4*)(Wg + (size_t)(kc+kk)*HID + hbase + c4*4);
                    *(float4*)(ws + kk*WS_STRIDE + c4*4) = v;
                }
                __syncthreads();
                const float* a0p = obs_s + (ty     )*OBS_STRIDE + kc;
                const float* a1p = obs_s + (ty + 16)*OBS_STRIDE + kc;
                const float* a2p = obs_s + (ty + 32)*OBS_STRIDE + kc;
                const float* a3p = obs_s + (ty + 48)*OBS_STRIDE + kc;
                #pragma unroll 8
                for (int k = 0; k < 64; ++k) {
                    float av[4], bv[4];
                    av[0] = a0p[k]; av[1] = a1p[k]; av[2] = a2p[k]; av[3] = a3p[k];
                    bv[0] = ws[k*WS_STRIDE + tx     ];
                    bv[1] = ws[k*WS_STRIDE + tx + 16];
                    bv[2] = ws[k*WS_STRIDE + tx + 32];
                    bv[3] = ws[k*WS_STRIDE + tx + 48];
                    #pragma unroll
                    for (int i = 0; i < 4; ++i)
                        #pragma unroll
                        for (int jj = 0; jj < 4; ++jj)
                            acc[i][jj] += av[i]*bv[jj];
                }
            }
            __syncthreads();
            // relu (+bias for meta net), stage into hs
            #pragma unroll
            for (int i = 0; i < 4; ++i) {
                int r = ty + 16*i;
                #pragma unroll
                for (int jj = 0; jj < 4; ++jj) {
                    int c = tx + 16*jj;
                    float v = acc[i][jj];
                    if (net == 0) v += bias_s[c];
                    hs[r*HS_STRIDE + c] = fmaxf(v, 0.f);
                }
            }
            __syncthreads();
            // contract hidden tile into heads
            if (net == 0) {
                #pragma unroll 4
                for (int c = 0; c < TN; ++c) {
                    float hv = hs[row4*HS_STRIDE + c];
                    m0 += hv * hw[c*HW_STRIDE + j4];
                    m1 += hv * hw[c*HW_STRIDE + j4 + 4];
                    if (j4 == 0) m2 += hv * hw[c*HW_STRIDE + 8];
                }
            } else {
                #pragma unroll 4
                for (int c = 0; c < TN; ++c) {
                    float hv = hs[row4*HS_STRIDE + c];
                    t0 += hv * hw[c*HW_STRIDE + 9  + j4];
                    t1 += hv * hw[c*HW_STRIDE + 13 + j4];
                }
            }
        }
    }

    // finals into hs: fin[r][0..7]=meta logits, [8]=value, [9..16]=term logits
    __syncthreads();
    hs[row4*HS_STRIDE + j4    ] = m0;
    hs[row4*HS_STRIDE + j4 + 4] = m1;
    if (j4 == 0) hs[row4*HS_STRIDE + 8] = m2;
    hs[row4*HS_STRIDE + 9  + j4] = t0;
    hs[row4*HS_STRIDE + 13 + j4] = t1;

    int* s_cnt  = icnt;
    int* s_base = icnt + 8;
    if (t < NOPT) s_cnt[t] = 0;
    __syncthreads();

    int myno = 0, mypos = 0, g = -1;
    if (t < TB) {
        g = g0 + t;
        float lg[8];
        #pragma unroll
        for (int o = 0; o < 8; ++o) lg[o] = hs[t*HS_STRIDE + o];
        float m = lg[0]; int am = 0;
        #pragma unroll
        for (int o = 1; o < 8; ++o) if (lg[o] > m) { m = lg[o]; am = o; }
        float s = 0.f;
        #pragma unroll
        for (int o = 0; o < 8; ++o) s += expf(lg[o] - m);
        float lp = -logf(s);
        float mv = hs[t*HS_STRIDE + 8];
        int eo = exec_opt[g];
        float tl = hs[t*HS_STRIDE + 9 + eo];
        float tp = 1.0f/(1.0f + expf(-tl));
        bool dn = (dones[g] != 0);
        bool term = dn || (tp > 0.5f);
        myno = term ? am : eo;
        out[3*B_AG + g] = (float)am;
        out[4*B_AG + g] = mv;
        out[5*B_AG + g] = lp;
        out[6*B_AG + g] = tp;
        mypos = atomicAdd(&s_cnt[myno], 1);
    }
    __syncthreads();
    if (t < NOPT) s_base[t] = atomicAdd(&g_opt_cnt[t], s_cnt[t]);
    __syncthreads();
    if (t < TB) {
        g_opt_list[myno*B_AG + s_base[myno] + mypos] = g;
    }
}

// ---------------------------------------------------------------------------
// Phase B: per-option sub-policy on compacted agent lists. grid (512, 8);
// blocks past an option's count exit immediately.
// ---------------------------------------------------------------------------
__global__ void __launch_bounds__(NTHREADS, 1)
subpolicy_kernel(const float* __restrict__ obs,
                 const float* __restrict__ W1,
                 const float* __restrict__ b1,
                 const float* __restrict__ Wpi,
                 const float* __restrict__ Wv,
                 float* __restrict__ out)
{
    const int opt   = blockIdx.y;
    const int start = blockIdx.x * TB;
    const int cnt   = g_opt_cnt[opt];
    if (start >= cnt) return;
    const int nvalid = min(TB, cnt - start);

    extern __shared__ float sm[];
    float* obs_s  = sm + OBS_OFF;
    float* ws     = sm + WS_OFF;
    float* hs     = sm + HS_OFF;
    float* hw     = sm + HW_OFF;
    float* bias_s = sm + MISC_OFF;
    int*   idx_s  = (int*)(sm + MISC_OFF + 64);  // 64 ints

    const int t    = threadIdx.x;
    const int tx   = t & 15;
    const int ty   = t >> 4;
    const int row4 = t >> 2;
    const int j4   = t & 3;

    if (t < TB) {
        int src = opt*B_AG + start + ((t < nvalid) ? t : 0);
        idx_s[t] = g_opt_list[src];
    }
    __syncthreads();

    for (int i = t; i < TB*(DID/4); i += NTHREADS) {
        int r = i >> 7, c4 = i & 127;
        float4 v = *(const float4*)(obs + (size_t)idx_s[r]*DID + c4*4);
        *(float4*)(obs_s + r*OBS_STRIDE + c4*4) = v;
    }

    const float* Wg   = W1  + (size_t)opt*DID*HID;
    const float* bg   = b1  + (size_t)opt*HID;
    const float* wpig = Wpi + (size_t)opt*HID*NACT;
    const float* wvg  = Wv  + (size_t)opt*HID;

    float h0 = 0.f, h1 = 0.f, h2 = 0.f, h3 = 0.f, hval = 0.f;

    for (int ht = 0; ht < HID/TN; ++ht) {
        const int hbase = ht * TN;
        __syncthreads();
        if (t < TN) {
            const float* wp = wpig + (size_t)(hbase + t)*NACT;
            #pragma unroll
            for (int a = 0; a < NACT; ++a) hw[t*HW_STRIDE + a] = wp[a];
            hw[t*HW_STRIDE + 16] = wvg[hbase + t];
            bias_s[t] = bg[hbase + t];
        }

        float acc[4][4];
        #pragma unroll
        for (int i = 0; i < 4; ++i)
            #pragma unroll
            for (int jj = 0; jj < 4; ++jj) acc[i][jj] = 0.f;

        for (int kc = 0; kc < DID; kc += 64) {
            __syncthreads();
            for (int i = t; i < 64*16; i += NTHREADS) {
                int kk = i >> 4, c4 = i & 15;
                float4 v = *(const float4*)(Wg + (size_t)(kc+kk)*HID + hbase + c4*4);
                *(float4*)(ws + kk*WS_STRIDE + c4*4) = v;
            }
            __syncthreads();
            const float* a0p = obs_s + (ty     )*OBS_STRIDE + kc;
            const float* a1p = obs_s + (ty + 16)*OBS_STRIDE + kc;
            const float* a2p = obs_s + (ty + 32)*OBS_STRIDE + kc;
            const float* a3p = obs_s + (ty + 48)*OBS_STRIDE + kc;
            #pragma unroll 8
            for (int k = 0; k < 64; ++k) {
                float av[4], bv[4];
                av[0] = a0p[k]; av[1] = a1p[k]; av[2] = a2p[k]; av[3] = a3p[k];
                bv[0] = ws[k*WS_STRIDE + tx     ];
                bv[1] = ws[k*WS_STRIDE + tx + 16];
                bv[2] = ws[k*WS_STRIDE + tx + 32];
                bv[3] = ws[k*WS_STRIDE + tx + 48];
                #pragma unroll
                for (int i = 0; i < 4; ++i)
                    #pragma unroll
                    for (int jj = 0; jj < 4; ++jj)
                        acc[i][jj] += av[i]*bv[jj];
            }
        }
        __syncthreads();
        #pragma unroll
        for (int i = 0; i < 4; ++i) {
            int r = ty + 16*i;
            #pragma unroll
            for (int jj = 0; jj < 4; ++jj) {
                int c = tx + 16*jj;
                hs[r*HS_STRIDE + c] = fmaxf(acc[i][jj] + bias_s[c], 0.f);
            }
        }
        __syncthreads();
        #pragma unroll 4
        for (int c = 0; c < TN; ++c) {
            float hv = hs[row4*HS_STRIDE + c];
            h0 += hv * hw[c*HW_STRIDE + j4     ];
            h1 += hv * hw[c*HW_STRIDE + j4 + 4 ];
            h2 += hv * hw[c*HW_STRIDE + j4 + 8 ];
            h3 += hv * hw[c*HW_STRIDE + j4 + 12];
            if (j4 == 0) hval += hv * hw[c*HW_STRIDE + 16];
        }
    }

    __syncthreads();
    hs[row4*HS_STRIDE + j4     ] = h0;
    hs[row4*HS_STRIDE + j4 + 4 ] = h1;
    hs[row4*HS_STRIDE + j4 + 8 ] = h2;
    hs[row4*HS_STRIDE + j4 + 12] = h3;
    if (j4 == 0) hs[row4*HS_STRIDE + 16] = hval;
    __syncthreads();

    if (t < nvalid) {
        int g = idx_s[t];
        float lg[16];
        #pragma unroll
        for (int a = 0; a < NACT; ++a) lg[a] = hs[t*HS_STRIDE + a];
        float m = lg[0]; int am = 0;
        #pragma unroll
        for (int a = 1; a < NACT; ++a) if (lg[a] > m) { m = lg[a]; am = a; }
        float s = 0.f;
        #pragma unroll
        for (int a = 0; a < NACT; ++a) s += expf(lg[a] - m);
        float lp = -logf(s);
        float val = hs[t*HS_STRIDE + 16];
        out[          g] = (float)am;
        out[  B_AG +  g] = val;
        out[2*B_AG +  g] = lp;
    }
}

extern "C" void kernel_launch(void* const* d_in, const int* in_sizes, int n_in,
                              void* d_out, int out_size) {
    const float* obs      = (const float*)d_in[0];
    const int*   dones    = (const int*)  d_in[1];
    const int*   exec_opt = (const int*)  d_in[2];
    const float* Wm1      = (const float*)d_in[3];
    const float* bm1      = (const float*)d_in[4];
    const float* Wm_pi    = (const float*)d_in[5];
    const float* Wm_v     = (const float*)d_in[6];
    const float* Wt1      = (const float*)d_in[7];
    const float* Wt2      = (const float*)d_in[8];
    const float* W1       = (const float*)d_in[9];
    const float* b1       = (const float*)d_in[10];
    const float* Wpi      = (const float*)d_in[11];
    const float* Wv       = (const float*)d_in[12];
    float* out = (float*)d_out;

    cudaFuncSetAttribute(meta_term_kernel,
                         cudaFuncAttributeMaxDynamicSharedMemorySize, SMEM_BYTES);
    cudaFuncSetAttribute(subpolicy_kernel,
                         cudaFuncAttributeMaxDynamicSharedMemorySize, SMEM_BYTES);

    init_kernel<<<1, 32>>>();
    meta_term_kernel<<<B_AG/TB, NTHREADS, SMEM_BYTES>>>(
        obs, dones, exec_opt, Wm1, bm1, Wm_pi, Wm_v, Wt1, Wt2, out);
    dim3 gB(B_AG/TB, NOPT);
    subpolicy_kernel<<<gB, NTHREADS, SMEM_BYTES>>>(obs, W1, b1, Wpi, Wv, out);
}

// round 2
// speedup vs baseline: 1.9619x; 1.9619x over previous
#include <cuda_runtime.h>
#include <math.h>
#include <stdint.h>

#define B_AG 32768
#define DID  512
#define HID  1024
#define NOPT 8
#define NACT 16

#define TB 64
#define TN 128
#define KC 32
#define NT 256
#define NCHUNK (DID/KC)   // 16

#define OS  36            // obs smem row stride (floats)
#define WSS 132           // weight smem row stride (floats)
#define HWS 20            // head-weight stride

#define OBS_BUF_F (TB*OS)            // 2304
#define WS_BUF_F  (KC*WSS)           // 4224
#define OBS_OFF 0
#define WS_OFF  (OBS_OFF + 2*OBS_BUF_F)   // 4608
#define HW_OFF  (WS_OFF + 2*WS_BUF_F)     // 13056
#define BIAS_OFF (HW_OFF + TN*HWS)        // 15616
#define FIN_OFF  (BIAS_OFF + TN)          // 15744
#define MISC_OFF (FIN_OFF + TB*HWS)       // 17024
#define SMEM_FLOATS (MISC_OFF + 96)       // 17120
#define SMEM_BYTES  (SMEM_FLOATS*4)       // 68480

__device__ int g_opt_cnt[NOPT];
__device__ int g_opt_list[NOPT*B_AG];

__global__ void init_kernel() {
    if (threadIdx.x < NOPT) g_opt_cnt[threadIdx.x] = 0;
}

// ---------------------------------------------------------------------------
// helpers: packed fp32 FMA (FFMA2) + cp.async
// ---------------------------------------------------------------------------
__device__ __forceinline__ unsigned long long pack2(float x) {
    unsigned long long r;
    asm("mov.b64 %0, {%1, %1};" : "=l"(r) : "f"(x));
    return r;
}
__device__ __forceinline__ float2 unpack2(unsigned long long v) {
    float2 f;
    asm("mov.b64 {%0, %1}, %2;" : "=f"(f.x), "=f"(f.y) : "l"(v));
    return f;
}
__device__ __forceinline__ void fma2(unsigned long long& d,
                                     unsigned long long a,
                                     unsigned long long b) {
    asm("fma.rn.f32x2 %0, %1, %2, %3;" : "=l"(d) : "l"(a), "l"(b), "l"(d));
}
__device__ __forceinline__ void cp16(uint32_t dst, const float* src) {
    asm volatile("cp.async.cg.shared.global [%0], [%1], 16;" :: "r"(dst), "l"(src));
}
#define CP_COMMIT() asm volatile("cp.async.commit_group;")
#define CP_WAIT1()  asm volatile("cp.async.wait_group 1;")
#define CP_WAIT0()  asm volatile("cp.async.wait_group 0;")

// ---------------------------------------------------------------------------
// Core: one [64 x 128] hidden tile, K=512, cp.async double-buffered chunks.
// acc[i][j] = f32x2 over (row ty+16i, cols 2*(tx+16j)..+1). Ends synced.
// ---------------------------------------------------------------------------
__device__ __forceinline__ void gemm_htile(float* __restrict__ sm,
    const float* __restrict__ gobs0, const float* __restrict__ gobs1,
    const float* __restrict__ wg, int t, unsigned long long acc[4][4])
{
    const int tx = t & 15, ty = t >> 4;
    const uint32_t su = (uint32_t)__cvta_generic_to_shared(sm);
    const uint32_t o_d0 = su + (uint32_t)((OBS_OFF + (t>>3)*OS        + (t&7)*4)*4);
    const uint32_t o_d1 = su + (uint32_t)((OBS_OFF + ((t+NT)>>3)*OS   + (t&7)*4)*4);
    const uint32_t w_d  = su + (uint32_t)((WS_OFF  + (t>>5)*WSS       + (t&31)*4)*4);

    // prologue: chunk 0 -> buffer 0
    cp16(o_d0, gobs0);
    cp16(o_d1, gobs1);
    #pragma unroll
    for (int j = 0; j < 4; ++j) cp16(w_d + j*(8*WSS*4), wg + j*8*HID);
    CP_COMMIT();

    #pragma unroll 1
    for (int kc = 0; kc < NCHUNK; ++kc) {
        const int cur = kc & 1;
        if (kc < NCHUNK-1) {
            const int nxt = cur ^ 1;
            const float* go0 = gobs0 + (kc+1)*KC;
            const float* go1 = gobs1 + (kc+1)*KC;
            const float* gw  = wg + (kc+1)*KC*HID;
            cp16(o_d0 + nxt*(OBS_BUF_F*4), go0);
            cp16(o_d1 + nxt*(OBS_BUF_F*4), go1);
            #pragma unroll
            for (int j = 0; j < 4; ++j)
                cp16(w_d + nxt*(WS_BUF_F*4) + j*(8*WSS*4), gw + j*8*HID);
            CP_COMMIT();
            CP_WAIT1();
        } else {
            CP_WAIT0();
        }
        __syncthreads();

        const float* ob = sm + OBS_OFF + cur*OBS_BUF_F;
        const float* wb = sm + WS_OFF  + cur*WS_BUF_F;
        const float* a0p = ob + (ty     )*OS;
        const float* a1p = ob + (ty + 16)*OS;
        const float* a2p = ob + (ty + 32)*OS;
        const float* a3p = ob + (ty + 48)*OS;
        const float* bbp = wb + 2*tx;

        #pragma unroll 8
        for (int k = 0; k < KC; ++k) {
            unsigned long long ap0 = pack2(a0p[k]);
            unsigned long long ap1 = pack2(a1p[k]);
            unsigned long long ap2 = pack2(a2p[k]);
            unsigned long long ap3 = pack2(a3p[k]);
            const float* bk = bbp + k*WSS;
            unsigned long long b0 = *(const unsigned long long*)(bk);
            unsigned long long b1 = *(const unsigned long long*)(bk + 32);
            unsigned long long b2 = *(const unsigned long long*)(bk + 64);
            unsigned long long b3 = *(const unsigned long long*)(bk + 96);
            fma2(acc[0][0], ap0, b0); fma2(acc[0][1], ap0, b1);
            fma2(acc[0][2], ap0, b2); fma2(acc[0][3], ap0, b3);
            fma2(acc[1][0], ap1, b0); fma2(acc[1][1], ap1, b1);
            fma2(acc[1][2], ap1, b2); fma2(acc[1][3], ap1, b3);
            fma2(acc[2][0], ap2, b0); fma2(acc[2][1], ap2, b1);
            fma2(acc[2][2], ap2, b2); fma2(acc[2][3], ap2, b3);
            fma2(acc[3][0], ap3, b0); fma2(acc[3][1], ap3, b1);
            fma2(acc[3][2], ap3, b2); fma2(acc[3][3], ap3, b3);
        }
        __syncthreads();
    }
}

// bias+relu acc -> hs staging (aliases the ws buffers, which are idle now)
__device__ __forceinline__ void stage_relu(float* __restrict__ sm,
    const unsigned long long acc[4][4], int t, bool use_bias)
{
    const int tx = t & 15, ty = t >> 4;
    float* hs = sm + WS_OFF;
    const float* bias_s = sm + BIAS_OFF;
    #pragma unroll
    for (int i = 0; i < 4; ++i) {
        int r = ty + 16*i;
        #pragma unroll
        for (int j = 0; j < 4; ++j) {
            int c = 2*(tx + 16*j);
            float2 v = unpack2(acc[i][j]);
            float b0 = use_bias ? bias_s[c]   : 0.f;
            float b1 = use_bias ? bias_s[c+1] : 0.f;
            v.x = fmaxf(v.x + b0, 0.f);
            v.y = fmaxf(v.y + b1, 0.f);
            *(float2*)(hs + r*WSS + c) = v;
        }
    }
}

// ---------------------------------------------------------------------------
// Phase A: fused meta + termination nets, writes meta outputs and builds the
// per-option compacted agent lists.
// ---------------------------------------------------------------------------
__global__ void __launch_bounds__(NT, 2)
meta_term_kernel(const float* __restrict__ obs,
                 const int*   __restrict__ dones,
                 const int*   __restrict__ exec_opt,
                 const float* __restrict__ Wm1,
                 const float* __restrict__ bm1,
                 const float* __restrict__ Wm_pi,
                 const float* __restrict__ Wm_v,
                 const float* __restrict__ Wt1,
                 const float* __restrict__ Wt2,
                 float* __restrict__ out)
{
    extern __shared__ float sm[];
    const int t  = threadIdx.x;
    const int g0 = blockIdx.x * TB;
    float* hw     = sm + HW_OFF;
    float* bias_s = sm + BIAS_OFF;
    float* fin    = sm + FIN_OFF;
    float* hs     = sm + WS_OFF;
    int*   icnt   = (int*)(sm + MISC_OFF);

    const int row4 = t >> 2, j4 = t & 3;

    const float* gobs0 = obs + (size_t)(g0 + (t>>3))*DID        + (t&7)*4;
    const float* gobs1 = obs + (size_t)(g0 + ((t+NT)>>3))*DID   + (t&7)*4;

    float m0 = 0.f, m1 = 0.f, m2 = 0.f, t0 = 0.f, t1 = 0.f;

    #pragma unroll 1
    for (int net = 0; net < 2; ++net) {
        const float* Wg = net ? Wt1 : Wm1;
        #pragma unroll 1
        for (int ht = 0; ht < HID/TN; ++ht) {
            const int hbase = ht * TN;
            __syncthreads();      // hw/bias free of previous readers
            if (t < TN) {
                if (net == 0) {
                    const float* wp = Wm_pi + (size_t)(hbase + t)*NOPT;
                    #pragma unroll
                    for (int o = 0; o < NOPT; ++o) hw[t*HWS + o] = wp[o];
                    hw[t*HWS + 8] = Wm_v[hbase + t];
                    bias_s[t] = bm1[hbase + t];
                } else {
                    const float* wp = Wt2 + (size_t)(hbase + t)*NOPT;
                    #pragma unroll
                    for (int o = 0; o < NOPT; ++o) hw[t*HWS + o] = wp[o];
                }
            }
            unsigned long long acc[4][4];
            #pragma unroll
            for (int i = 0; i < 4; ++i)
                #pragma unroll
                for (int j = 0; j < 4; ++j) acc[i][j] = 0ull;

            const float* wg = Wg + hbase + (size_t)(t>>5)*HID + (t&31)*4;
            gemm_htile(sm, gobs0, gobs1, wg, t, acc);
            stage_relu(sm, acc, t, net == 0);
            __syncthreads();

            if (net == 0) {
                #pragma unroll 8
                for (int c = 0; c < TN; ++c) {
                    float hv = hs[row4*WSS + c];
                    m0 += hv * hw[c*HWS + j4];
                    m1 += hv * hw[c*HWS + j4 + 4];
                    if (j4 == 0) m2 += hv * hw[c*HWS + 8];
                }
            } else {
                #pragma unroll 8
                for (int c = 0; c < TN; ++c) {
                    float hv = hs[row4*WSS + c];
                    t0 += hv * hw[c*HWS + j4];
                    t1 += hv * hw[c*HWS + j4 + 4];
                }
            }
        }
    }

    // finals: fin[r][0..7]=meta logits, [8]=value, [9..16]=term logits
    fin[row4*HWS + j4    ] = m0;
    fin[row4*HWS + j4 + 4] = m1;
    if (j4 == 0) fin[row4*HWS + 8] = m2;
    fin[row4*HWS + 9  + j4] = t0;
    fin[row4*HWS + 13 + j4] = t1;

    int* s_cnt  = icnt + 64;
    int* s_base = icnt + 72;
    if (t < NOPT) s_cnt[t] = 0;
    __syncthreads();

    int myno = 0, mypos = 0;
    if (t < TB) {
        int g = g0 + t;
        float lg[8];
        #pragma unroll
        for (int o = 0; o < 8; ++o) lg[o] = fin[t*HWS + o];
        float m = lg[0]; int am = 0;
        #pragma unroll
        for (int o = 1; o < 8; ++o) if (lg[o] > m) { m = lg[o]; am = o; }
        float s = 0.f;
        #pragma unroll
        for (int o = 0; o < 8; ++o) s += expf(lg[o] - m);
        float lp = -logf(s);
        float mv = fin[t*HWS + 8];
        int eo = exec_opt[g];
        float tl = fin[t*HWS + 9 + eo];
        float tp = 1.0f/(1.0f + expf(-tl));
        bool dn = (dones[g] != 0);
        bool term = dn || (tp > 0.5f);
        myno = term ? am : eo;
        out[3*B_AG + g] = (float)am;
        out[4*B_AG + g] = mv;
        out[5*B_AG + g] = lp;
        out[6*B_AG + g] = tp;
        mypos = atomicAdd(&s_cnt[myno], 1);
    }
    __syncthreads();
    if (t < NOPT) s_base[t] = atomicAdd(&g_opt_cnt[t], s_cnt[t]);
    __syncthreads();
    if (t < TB) {
        g_opt_list[myno*B_AG + s_base[myno] + mypos] = g0 + t;
    }
}

// ---------------------------------------------------------------------------
// Phase B: per-option sub-policy on compacted lists.
// ---------------------------------------------------------------------------
__global__ void __launch_bounds__(NT, 2)
subpolicy_kernel(const float* __restrict__ obs,
                 const float* __restrict__ W1,
                 const float* __restrict__ b1,
                 const float* __restrict__ Wpi,
                 const float* __restrict__ Wv,
                 float* __restrict__ out)
{
    const int opt   = blockIdx.y;
    const int start = blockIdx.x * TB;
    const int cnt   = g_opt_cnt[opt];
    if (start >= cnt) return;
    const int nvalid = min(TB, cnt - start);

    extern __shared__ float sm[];
    const int t = threadIdx.x;
    float* hw     = sm + HW_OFF;
    float* bias_s = sm + BIAS_OFF;
    float* fin    = sm + FIN_OFF;
    float* hs     = sm + WS_OFF;
    int*   idx_s  = (int*)(sm + MISC_OFF);

    const int row4 = t >> 2, j4 = t & 3;

    if (t < TB) {
        int src = opt*B_AG + start + ((t < nvalid) ? t : 0);
        idx_s[t] = g_opt_list[src];
    }
    __syncthreads();

    const float* gobs0 = obs + (size_t)idx_s[t>>3]*DID      + (t&7)*4;
    const float* gobs1 = obs + (size_t)idx_s[(t+NT)>>3]*DID + (t&7)*4;

    const float* Wg   = W1  + (size_t)opt*DID*HID;
    const float* bg   = b1  + (size_t)opt*HID;
    const float* wpig = Wpi + (size_t)opt*HID*NACT;
    const float* wvg  = Wv  + (size_t)opt*HID;

    float h0 = 0.f, h1 = 0.f, h2 = 0.f, h3 = 0.f, hval = 0.f;

    #pragma unroll 1
    for (int ht = 0; ht < HID/TN; ++ht) {
        const int hbase = ht * TN;
        __syncthreads();
        if (t < TN) {
            const float* wp = wpig + (size_t)(hbase + t)*NACT;
            #pragma unroll
            for (int a = 0; a < NACT; ++a) hw[t*HWS + a] = wp[a];
            hw[t*HWS + 16] = wvg[hbase + t];
            bias_s[t] = bg[hbase + t];
        }
        unsigned long long acc[4][4];
        #pragma unroll
        for (int i = 0; i < 4; ++i)
            #pragma unroll
            for (int j = 0; j < 4; ++j) acc[i][j] = 0ull;

        const float* wg = Wg + hbase + (size_t)(t>>5)*HID + (t&31)*4;
        gemm_htile(sm, gobs0, gobs1, wg, t, acc);
        stage_relu(sm, acc, t, true);
        __syncthreads();

        #pragma unroll 8
        for (int c = 0; c < TN; ++c) {
            float hv = hs[row4*WSS + c];
            h0 += hv * hw[c*HWS + j4     ];
            h1 += hv * hw[c*HWS + j4 + 4 ];
            h2 += hv * hw[c*HWS + j4 + 8 ];
            h3 += hv * hw[c*HWS + j4 + 12];
            if (j4 == 0) hval += hv * hw[c*HWS + 16];
        }
    }

    fin[row4*HWS + j4     ] = h0;
    fin[row4*HWS + j4 + 4 ] = h1;
    fin[row4*HWS + j4 + 8 ] = h2;
    fin[row4*HWS + j4 + 12] = h3;
    if (j4 == 0) fin[row4*HWS + 16] = hval;
    __syncthreads();

    if (t < nvalid) {
        int g = idx_s[t];
        float lg[16];
        #pragma unroll
        for (int a = 0; a < NACT; ++a) lg[a] = fin[t*HWS + a];
        float m = lg[0]; int am = 0;
        #pragma unroll
        for (int a = 1; a < NACT; ++a) if (lg[a] > m) { m = lg[a]; am = a; }
        float s = 0.f;
        #pragma unroll
        for (int a = 0; a < NACT; ++a) s += expf(lg[a] - m);
        float lp = -logf(s);
        float val = fin[t*HWS + 16];
        out[          g] = (float)am;
        out[  B_AG +  g] = val;
        out[2*B_AG +  g] = lp;
    }
}

extern "C" void kernel_launch(void* const* d_in, const int* in_sizes, int n_in,
                              void* d_out, int out_size) {
    const float* obs      = (const float*)d_in[0];
    const int*   dones    = (const int*)  d_in[1];
    const int*   exec_opt = (const int*)  d_in[2];
    const float* Wm1      = (const float*)d_in[3];
    const float* bm1      = (const float*)d_in[4];
    const float* Wm_pi    = (const float*)d_in[5];
    const float* Wm_v     = (const float*)d_in[6];
    const float* Wt1      = (const float*)d_in[7];
    const float* Wt2      = (const float*)d_in[8];
    const float* W1       = (const float*)d_in[9];
    const float* b1       = (const float*)d_in[10];
    const float* Wpi      = (const float*)d_in[11];
    const float* Wv       = (const float*)d_in[12];
    float* out = (float*)d_out;

    cudaFuncSetAttribute(meta_term_kernel,
                         cudaFuncAttributeMaxDynamicSharedMemorySize, SMEM_BYTES);
    cudaFuncSetAttribute(subpolicy_kernel,
                         cudaFuncAttributeMaxDynamicSharedMemorySize, SMEM_BYTES);

    init_kernel<<<1, 32>>>();
    meta_term_kernel<<<B_AG/TB, NT, SMEM_BYTES>>>(
        obs, dones, exec_opt, Wm1, bm1, Wm_pi, Wm_v, Wt1, Wt2, out);
    dim3 gB(B_AG/TB, NOPT);
    subpolicy_kernel<<<gB, NT, SMEM_BYTES>>>(obs, W1, b1, Wpi, Wv, out);
}